// round 1
// baseline (speedup 1.0000x reference)
#include <cuda_runtime.h>

#define NC 32
#define RES0 512
#define NLEV 6
#define TOTAL 349440   // sum of res^2 over 6 levels

// Pool: [face][texel(level-major)][channel], float, 268 MB
__device__ float POOL[6ll * TOTAL * NC];
// Scratch: unfiltered pooled levels 1..5, channel-last. 67 MB
__device__ float SCRATCH[523776ll * NC];

__constant__ int d_offs[NLEV] = {0, 262144, 327680, 344064, 348160, 349184};

// ---------------------------------------------------------------------------
// K1: transpose feature (C,6,512,512) -> pool level0 (channel-last)
//     AND compute level-1 avg-pool into SCRATCH (fused, saves one 201MB pass)
// Tile: 2 rows x 64 cols per block.
// ---------------------------------------------------------------------------
__global__ void k_transpose_pool1(const float* __restrict__ feat) {
    int f = blockIdx.z;
    int x0 = blockIdx.x * 64;
    int y0 = blockIdx.y * 2;
    __shared__ float s[32 * 129];
    int tid = threadIdx.x;

    for (int i = tid; i < 32 * 128; i += 256) {
        int c = i >> 7, t = i & 127;
        int yy = y0 + (t >> 6), xx = x0 + (t & 63);
        s[c * 129 + t] = feat[(((size_t)c * 6 + f) * 512 + yy) * 512 + xx];
    }
    __syncthreads();

    float4* P4 = (float4*)POOL;
    for (int i = tid; i < 1024; i += 256) {
        int t = i >> 3, q = i & 7;
        int yy = y0 + (t >> 6), xx = x0 + (t & 63);
        float4 v;
        v.x = s[(4 * q + 0) * 129 + t];
        v.y = s[(4 * q + 1) * 129 + t];
        v.z = s[(4 * q + 2) * 129 + t];
        v.w = s[(4 * q + 3) * 129 + t];
        P4[((size_t)f * TOTAL + (size_t)yy * 512 + xx) * 8 + q] = v;
    }
    // level-1 pool: output row y0/2, cols x0/2 .. x0/2+31
    for (int i = tid; i < 1024; i += 256) {
        int c = i & 31, to = i >> 5;
        int t00 = 2 * to, t10 = 64 + 2 * to;
        float v = 0.25f * (s[c * 129 + t00] + s[c * 129 + t00 + 1] +
                           s[c * 129 + t10] + s[c * 129 + t10 + 1]);
        SCRATCH[(((size_t)f * 65536 + (size_t)(y0 >> 1) * 256 + (x0 >> 1) + to) * 32) + c] = v;
    }
}

// ---------------------------------------------------------------------------
// Generic 2x2 avg pool inside SCRATCH (channel-last, float4-vectorized)
// ---------------------------------------------------------------------------
__global__ void k_pool(int Rin, size_t inOff, size_t outOff) {
    int Rout = Rin >> 1;
    long idx = (long)blockIdx.x * 256 + threadIdx.x;
    long total = 6l * Rout * Rout * 8;
    if (idx >= total) return;
    int q = (int)(idx & 7);
    long t = idx >> 3;
    int fa = (int)(t / ((long)Rout * Rout));
    int rem = (int)(t - (long)fa * Rout * Rout);
    int oy = rem / Rout, ox = rem % Rout;
    const float4* S4 = (const float4*)SCRATCH;
    size_t ib = (inOff + ((size_t)fa * Rin + 2 * oy) * Rin + 2 * ox) * 8 + q;
    float4 a = S4[ib];
    float4 b = S4[ib + 8];
    float4 c = S4[ib + (size_t)Rin * 8];
    float4 d = S4[ib + (size_t)Rin * 8 + 8];
    float4 o;
    o.x = 0.25f * (a.x + b.x + c.x + d.x);
    o.y = 0.25f * (a.y + b.y + c.y + d.y);
    o.z = 0.25f * (a.z + b.z + c.z + d.z);
    o.w = 0.25f * (a.w + b.w + c.w + d.w);
    ((float4*)SCRATCH)[(outOff + (size_t)t) * 8 + q] = o;
}

// ---------------------------------------------------------------------------
// GGX specular filter, 5x5, clamped borders. 8x8 output tile, 12x12 halo.
// Weights are face-independent: cos = (1 + u1*u2 + v1*v2)/(n1*n2).
// Weights precomputed once per tile into SMEM (kills 8x MUFU redundancy).
// ---------------------------------------------------------------------------
__global__ void k_filter(int R, size_t inOff, size_t poolOff, float a2) {
    int f = blockIdx.z;
    int x0 = blockIdx.x * 8, y0 = blockIdx.y * 8;
    __shared__ float4 hs[12 * 12 * 8];
    __shared__ float wts[64 * 25];
    __shared__ float wsn[64];
    int tid = threadIdx.x;
    const float4* S4 = (const float4*)SCRATCH;

    for (int i = tid; i < 12 * 12 * 8; i += 256) {
        int t = i >> 3, q = i & 7;
        int hy = t / 12, hx = t % 12;
        int gy = min(max(y0 - 2 + hy, 0), R - 1);
        int gx = min(max(x0 - 2 + hx, 0), R - 1);
        hs[i] = S4[(inOff + ((size_t)f * R + gy) * R + gx) * 8 + q];
    }

    float invR2 = 2.0f / (float)R;
    for (int i = tid; i < 1600; i += 256) {
        int t = i / 25, n = i % 25;
        int gy = y0 + (t >> 3), gx = x0 + (t & 7);
        int iy = min(max(gy + n / 5 - 2, 0), R - 1);
        int jx = min(max(gx + n % 5 - 2, 0), R - 1);
        float u = (gx + 0.5f) * invR2 - 1.f, v = (gy + 0.5f) * invR2 - 1.f;
        float uu = (jx + 0.5f) * invR2 - 1.f, vv = (iy + 0.5f) * invR2 - 1.f;
        float cs = (1.f + u * uu + v * vv) * rsqrtf(1.f + u * u + v * v) *
                   rsqrtf(1.f + uu * uu + vv * vv);
        cs = fminf(cs, 1.f);
        float w = 0.f;
        if (cs > 0.f) {
            float dn = cs * cs * (a2 - 1.f) + 1.f;
            w = a2 / (3.14159265358979f * dn * dn);
        }
        wts[i] = w;
    }
    __syncthreads();
    for (int i = tid; i < 64; i += 256) {
        float sum = 0.f;
#pragma unroll
        for (int n = 0; n < 25; n++) sum += wts[i * 25 + n];
        wsn[i] = 1.f / fmaxf(sum, 1e-8f);
    }
    __syncthreads();

    float4* P4 = (float4*)POOL;
#pragma unroll
    for (int p = 0; p < 2; p++) {
        int item = p * 256 + tid;
        int q = item & 7, t = item >> 3;
        int ty = t >> 3, tx = t & 7;
        float4 acc = make_float4(0.f, 0.f, 0.f, 0.f);
#pragma unroll
        for (int n = 0; n < 25; n++) {
            float w = wts[t * 25 + n];
            int hy = ty + n / 5, hx = tx + n % 5;
            float4 v = hs[(hy * 12 + hx) * 8 + q];
            acc.x += w * v.x; acc.y += w * v.y;
            acc.z += w * v.z; acc.w += w * v.w;
        }
        float ws = wsn[t];
        acc.x *= ws; acc.y *= ws; acc.z *= ws; acc.w *= ws;
        P4[((size_t)f * TOTAL + poolOff + (size_t)(y0 + ty) * R + (x0 + tx)) * 8 + q] = acc;
    }
}

// ---------------------------------------------------------------------------
// Fetch: 8 lanes per query, one float4 of channels per lane.
// All pool gathers are coalesced 128B lines; output store fully coalesced.
// ---------------------------------------------------------------------------
__global__ void k_fetch(const float* __restrict__ w, const float* __restrict__ rr,
                        float* __restrict__ out, int B) {
    long g = (long)blockIdx.x * 256 + threadIdx.x;
    if (g >= (long)B * 8) return;
    int b = (int)(g >> 3), q = (int)(g & 7);

    float dx = w[b * 3 + 0] * 2.f - 1.f;
    float dy = w[b * 3 + 1] * 2.f - 1.f;
    float dz = w[b * 3 + 2] * 2.f - 1.f;
    float ax = fabsf(dx), ay = fabsf(dy), az = fabsf(dz);
    bool cx = (ax >= ay) && (ax >= az);
    bool cy = (ay >= az) && !cx;
    float ma = cx ? ax : (cy ? ay : az);
    int face = cx ? (dx > 0.f ? 0 : 1) : (cy ? (dy > 0.f ? 2 : 3) : (dz > 0.f ? 4 : 5));
    float un = cx ? (dx > 0.f ? -dz : dz) : (cy ? dx : (dz > 0.f ? dx : -dx));
    float vn = cx ? -dy : (cy ? (dy > 0.f ? dz : -dz) : -dy);
    float inv = 1.f / ma;
    float u01 = (un * inv + 1.f) * 0.5f;
    float v01 = (vn * inv + 1.f) * 0.5f;

    float lev = fminf(fmaxf((rr[b] - 0.03f) * (1.f / 0.96f), 0.f), 1.f) * 5.f;
    int l0 = (int)lev;
    if (l0 > 5) l0 = 5;
    float t = lev - (float)l0;
    int l1 = min(l0 + 1, 5);

    const float4* P4 = (const float4*)POOL;
    size_t fb = (size_t)face * TOTAL;
    float4 acc = make_float4(0.f, 0.f, 0.f, 0.f);

#pragma unroll
    for (int s = 0; s < 2; s++) {
        int l = s ? l1 : l0;
        float wl = s ? t : (1.f - t);
        int res = 512 >> l;
        float rf = (float)res;
        float x = fminf(fmaxf(u01 * rf - 0.5f, 0.f), rf - 1.f);
        float y = fminf(fmaxf(v01 * rf - 0.5f, 0.f), rf - 1.f);
        int x0 = (int)x, y0 = (int)y;
        int x1 = min(x0 + 1, res - 1), y1 = min(y0 + 1, res - 1);
        float fx = x - (float)x0, fy = y - (float)y0;
        size_t row0 = (fb + d_offs[l] + (size_t)y0 * res) * 8 + q;
        size_t row1 = (fb + d_offs[l] + (size_t)y1 * res) * 8 + q;
        float4 g00 = P4[row0 + (size_t)x0 * 8];
        float4 g01 = P4[row0 + (size_t)x1 * 8];
        float4 g10 = P4[row1 + (size_t)x0 * 8];
        float4 g11 = P4[row1 + (size_t)x1 * 8];
        float w00 = wl * (1.f - fx) * (1.f - fy);
        float w01 = wl * fx * (1.f - fy);
        float w10 = wl * (1.f - fx) * fy;
        float w11 = wl * fx * fy;
        acc.x += w00 * g00.x + w01 * g01.x + w10 * g10.x + w11 * g11.x;
        acc.y += w00 * g00.y + w01 * g01.y + w10 * g10.y + w11 * g11.y;
        acc.z += w00 * g00.z + w01 * g01.z + w10 * g10.z + w11 * g11.z;
        acc.w += w00 * g00.w + w01 * g01.w + w10 * g10.w + w11 * g11.w;
    }
    ((float4*)out)[(size_t)b * 8 + q] = acc;
}

extern "C" void kernel_launch(void* const* d_in, const int* in_sizes, int n_in,
                              void* d_out, int out_size) {
    const float* feat = (const float*)d_in[0];
    const float* w    = (const float*)d_in[1];
    const float* r    = (const float*)d_in[2];
    float* out = (float*)d_out;
    int B = in_sizes[2];

    // 1. transpose + level1 pool (fused)
    k_transpose_pool1<<<dim3(8, 256, 6), 256>>>(feat);

    // 2. pooling cascade levels 2..5 (scratch texel offsets)
    k_pool<<<(6 * 128 * 128 * 8 + 255) / 256, 256>>>(256, 0,      393216);
    k_pool<<<(6 *  64 *  64 * 8 + 255) / 256, 256>>>(128, 393216, 491520);
    k_pool<<<(6 *  32 *  32 * 8 + 255) / 256, 256>>>( 64, 491520, 516096);
    k_pool<<<(6 *  16 *  16 * 8 + 255) / 256, 256>>>( 32, 516096, 522240);

    // 3. GGX filters levels 1..5
    const size_t SO[6] = {0, 0, 393216, 491520, 516096, 522240};
    const size_t PO[6] = {0, 262144, 327680, 344064, 348160, 349184};
    for (int l = 1; l < 6; l++) {
        int R = 512 >> l;
        float rf32 = (float)(0.03 + 0.192 * l);   // linspace(0.03,0.99,6)[l]
        double a = (double)rf32;
        float a2 = (float)(a * a * a * a);        // alpha^2 = rough^4
        k_filter<<<dim3(R / 8, R / 8, 6), 256>>>(R, SO[l], PO[l], a2);
    }

    // 4. fetch
    long nthreads = (long)B * 8;
    k_fetch<<<(unsigned)((nthreads + 255) / 256), 256>>>(w, r, out, B);
}

// round 2
// speedup vs baseline: 1.2914x; 1.2914x over previous
#include <cuda_runtime.h>
#include <cuda_fp16.h>

#define NC 32
#define NLEV 6
#define TOTAL 349440   // sum of res^2 over 6 levels

// Pool: [face][texel(level-major)][channel], HALF, 134 MB
__device__ __half POOLH[6ll * TOTAL * NC];
// Scratch: unfiltered pooled levels 1..5, channel-last fp32. 67 MB
__device__ float SCRATCH[523776ll * NC];

__constant__ int d_offs[NLEV] = {0, 262144, 327680, 344064, 348160, 349184};

// Fused-filter per-level tables (levels 1..5)
__constant__ int   F_start[6]  = {0, 6144, 7680, 8064, 8160, 8184};
__constant__ int   F_R[5]      = {256, 128, 64, 32, 16};
__constant__ int   F_inOff[5]  = {0, 393216, 491520, 516096, 522240};
__constant__ int   F_poolOff[5]= {262144, 327680, 344064, 348160, 349184};
__constant__ float F_a2[5]     = {0.00243101246f, 0.030233088f, 0.137822329f, 0.419904f, 0.96059601f}; // rough^4

// ---------------------------------------------------------------------------
// K1: transpose feature (C,6,512,512) -> pool level0 (half, channel-last)
//     AND compute level-1 avg-pool into SCRATCH (fused)
// ---------------------------------------------------------------------------
__global__ void k_transpose_pool1(const float* __restrict__ feat) {
    int f = blockIdx.z;
    int x0 = blockIdx.x * 64;
    int y0 = blockIdx.y * 2;
    __shared__ float s[32 * 129];
    int tid = threadIdx.x;

    // vectorized fill: 32ch x 128 texels = 1024 float4-less... use float4 loads
    for (int i = tid; i < 32 * 32; i += 256) {
        int c = i >> 5, v = i & 31;                 // v = vec index, 4 texels
        int t0 = v * 4;
        int yy = y0 + (t0 >> 6), xx = x0 + (t0 & 63);
        float4 d = *(const float4*)&feat[(((size_t)c * 6 + f) * 512 + yy) * 512 + xx];
        s[c * 129 + t0 + 0] = d.x;
        s[c * 129 + t0 + 1] = d.y;
        s[c * 129 + t0 + 2] = d.z;
        s[c * 129 + t0 + 3] = d.w;
    }
    __syncthreads();

    uint4* P4 = (uint4*)POOLH;   // one uint4 = 8 half channels
    for (int i = tid; i < 512; i += 256) {
        int t = i >> 2, q = i & 3;
        int yy = y0 + (t >> 6), xx = x0 + (t & 63);
        const float* sp = &s[(8 * q) * 129 + t];
        __half2 h0 = __floats2half2_rn(sp[0],       sp[129]);
        __half2 h1 = __floats2half2_rn(sp[2 * 129], sp[3 * 129]);
        __half2 h2 = __floats2half2_rn(sp[4 * 129], sp[5 * 129]);
        __half2 h3 = __floats2half2_rn(sp[6 * 129], sp[7 * 129]);
        uint4 o;
        o.x = *(unsigned*)&h0; o.y = *(unsigned*)&h1;
        o.z = *(unsigned*)&h2; o.w = *(unsigned*)&h3;
        P4[((size_t)f * TOTAL + (size_t)yy * 512 + xx) * 4 + q] = o;
    }
    // level-1 pool (fp32 scratch): output row y0/2, cols x0/2 .. +31
    for (int i = tid; i < 1024; i += 256) {
        int c = i & 31, to = i >> 5;
        int t00 = 2 * to, t10 = 64 + 2 * to;
        float v = 0.25f * (s[c * 129 + t00] + s[c * 129 + t00 + 1] +
                           s[c * 129 + t10] + s[c * 129 + t10 + 1]);
        SCRATCH[(((size_t)f * 65536 + (size_t)(y0 >> 1) * 256 + (x0 >> 1) + to) * 32) + c] = v;
    }
}

// ---------------------------------------------------------------------------
// Generic 2x2 avg pool inside SCRATCH (fp32, float4-vectorized)
// ---------------------------------------------------------------------------
__global__ void k_pool(int Rin, size_t inOff, size_t outOff) {
    int Rout = Rin >> 1;
    long idx = (long)blockIdx.x * 256 + threadIdx.x;
    long total = 6l * Rout * Rout * 8;
    if (idx >= total) return;
    int q = (int)(idx & 7);
    long t = idx >> 3;
    int fa = (int)(t / ((long)Rout * Rout));
    int rem = (int)(t - (long)fa * Rout * Rout);
    int oy = rem / Rout, ox = rem % Rout;
    const float4* S4 = (const float4*)SCRATCH;
    size_t ib = (inOff + ((size_t)fa * Rin + 2 * oy) * Rin + 2 * ox) * 8 + q;
    float4 a = S4[ib];
    float4 b = S4[ib + 8];
    float4 c = S4[ib + (size_t)Rin * 8];
    float4 d = S4[ib + (size_t)Rin * 8 + 8];
    float4 o;
    o.x = 0.25f * (a.x + b.x + c.x + d.x);
    o.y = 0.25f * (a.y + b.y + c.y + d.y);
    o.z = 0.25f * (a.z + b.z + c.z + d.z);
    o.w = 0.25f * (a.w + b.w + c.w + d.w);
    ((float4*)SCRATCH)[(outOff + (size_t)t) * 8 + q] = o;
}

// ---------------------------------------------------------------------------
// Fused GGX filter for all levels 1..5 (flattened grid).
// 5x5 window, clamped borders, 8x8 tile, 12x12 halo, half output.
// ---------------------------------------------------------------------------
__global__ void k_filter_all() {
    int bid = blockIdx.x;
    int li = 0;
    #pragma unroll
    for (int k = 1; k < 5; k++) if (bid >= F_start[k]) li = k;
    int R = F_R[li];
    int nb = R >> 3;
    int rel = bid - F_start[li];
    int f  = rel / (nb * nb);
    int r2 = rel - f * nb * nb;
    int y0 = (r2 / nb) * 8, x0 = (r2 % nb) * 8;
    size_t inOff  = (size_t)F_inOff[li];
    size_t poolOff= (size_t)F_poolOff[li];
    float a2 = F_a2[li];

    __shared__ float4 hs[12 * 12 * 8];
    __shared__ float wts[64 * 25];
    __shared__ float wsn[64];
    int tid = threadIdx.x;
    const float4* S4 = (const float4*)SCRATCH;

    for (int i = tid; i < 12 * 12 * 8; i += 256) {
        int t = i >> 3, q = i & 7;
        int hy = t / 12, hx = t % 12;
        int gy = min(max(y0 - 2 + hy, 0), R - 1);
        int gx = min(max(x0 - 2 + hx, 0), R - 1);
        hs[i] = S4[(inOff + ((size_t)f * R + gy) * R + gx) * 8 + q];
    }

    float invR2 = 2.0f / (float)R;
    for (int i = tid; i < 1600; i += 256) {
        int t = i / 25, n = i % 25;
        int gy = y0 + (t >> 3), gx = x0 + (t & 7);
        int iy = min(max(gy + n / 5 - 2, 0), R - 1);
        int jx = min(max(gx + n % 5 - 2, 0), R - 1);
        float u = (gx + 0.5f) * invR2 - 1.f, v = (gy + 0.5f) * invR2 - 1.f;
        float uu = (jx + 0.5f) * invR2 - 1.f, vv = (iy + 0.5f) * invR2 - 1.f;
        float cs = (1.f + u * uu + v * vv) * rsqrtf(1.f + u * u + v * v) *
                   rsqrtf(1.f + uu * uu + vv * vv);
        cs = fminf(cs, 1.f);
        float w = 0.f;
        if (cs > 0.f) {
            float dn = cs * cs * (a2 - 1.f) + 1.f;
            w = a2 / (3.14159265358979f * dn * dn);
        }
        wts[i] = w;
    }
    __syncthreads();
    for (int i = tid; i < 64; i += 256) {
        float sum = 0.f;
#pragma unroll
        for (int n = 0; n < 25; n++) sum += wts[i * 25 + n];
        wsn[i] = 1.f / fmaxf(sum, 1e-8f);
    }
    __syncthreads();

    // exactly 256 work items: 64 texels x 4 uint4-slots
    uint4* P4 = (uint4*)POOLH;
    int q = tid & 3, t = tid >> 2;
    int ty = t >> 3, tx = t & 7;
    float4 a0 = make_float4(0.f, 0.f, 0.f, 0.f);
    float4 a1 = make_float4(0.f, 0.f, 0.f, 0.f);
#pragma unroll
    for (int n = 0; n < 25; n++) {
        float w = wts[t * 25 + n];
        int hy = ty + n / 5, hx = tx + n % 5;
        float4 v0 = hs[(hy * 12 + hx) * 8 + 2 * q];
        float4 v1 = hs[(hy * 12 + hx) * 8 + 2 * q + 1];
        a0.x += w * v0.x; a0.y += w * v0.y; a0.z += w * v0.z; a0.w += w * v0.w;
        a1.x += w * v1.x; a1.y += w * v1.y; a1.z += w * v1.z; a1.w += w * v1.w;
    }
    float ws = wsn[t];
    __half2 h0 = __floats2half2_rn(a0.x * ws, a0.y * ws);
    __half2 h1 = __floats2half2_rn(a0.z * ws, a0.w * ws);
    __half2 h2 = __floats2half2_rn(a1.x * ws, a1.y * ws);
    __half2 h3 = __floats2half2_rn(a1.z * ws, a1.w * ws);
    uint4 o;
    o.x = *(unsigned*)&h0; o.y = *(unsigned*)&h1;
    o.z = *(unsigned*)&h2; o.w = *(unsigned*)&h3;
    P4[((size_t)f * TOTAL + poolOff + (size_t)(y0 + ty) * R + (x0 + tx)) * 4 + q] = o;
}

// ---------------------------------------------------------------------------
// Fetch: 4 lanes per query, one uint4 (8 half channels) per lane per tap.
// ---------------------------------------------------------------------------
__global__ void k_fetch(const float* __restrict__ w, const float* __restrict__ rr,
                        float* __restrict__ out, int B) {
    long g = (long)blockIdx.x * 256 + threadIdx.x;
    if (g >= (long)B * 4) return;
    int b = (int)(g >> 2), q = (int)(g & 3);

    float dx = w[b * 3 + 0] * 2.f - 1.f;
    float dy = w[b * 3 + 1] * 2.f - 1.f;
    float dz = w[b * 3 + 2] * 2.f - 1.f;
    float ax = fabsf(dx), ay = fabsf(dy), az = fabsf(dz);
    bool cx = (ax >= ay) && (ax >= az);
    bool cy = (ay >= az) && !cx;
    float ma = cx ? ax : (cy ? ay : az);
    int face = cx ? (dx > 0.f ? 0 : 1) : (cy ? (dy > 0.f ? 2 : 3) : (dz > 0.f ? 4 : 5));
    float un = cx ? (dx > 0.f ? -dz : dz) : (cy ? dx : (dz > 0.f ? dx : -dx));
    float vn = cx ? -dy : (cy ? (dy > 0.f ? dz : -dz) : -dy);
    float inv = 1.f / ma;
    float u01 = (un * inv + 1.f) * 0.5f;
    float v01 = (vn * inv + 1.f) * 0.5f;

    float lev = fminf(fmaxf((rr[b] - 0.03f) * (1.f / 0.96f), 0.f), 1.f) * 5.f;
    int l0 = (int)lev;
    if (l0 > 5) l0 = 5;
    float t = lev - (float)l0;
    int l1 = min(l0 + 1, 5);

    const uint4* P4 = (const uint4*)POOLH;
    size_t fb = (size_t)face * TOTAL;
    float acc[8];
#pragma unroll
    for (int k = 0; k < 8; k++) acc[k] = 0.f;

#pragma unroll
    for (int s = 0; s < 2; s++) {
        int l = s ? l1 : l0;
        float wl = s ? t : (1.f - t);
        int res = 512 >> l;
        float rf = (float)res;
        float x = fminf(fmaxf(u01 * rf - 0.5f, 0.f), rf - 1.f);
        float y = fminf(fmaxf(v01 * rf - 0.5f, 0.f), rf - 1.f);
        int x0 = (int)x, y0 = (int)y;
        int x1 = min(x0 + 1, res - 1), y1 = min(y0 + 1, res - 1);
        float fx = x - (float)x0, fy = y - (float)y0;
        size_t base = fb + d_offs[l];
        size_t r0 = (base + (size_t)y0 * res) * 4 + q;
        size_t r1 = (base + (size_t)y1 * res) * 4 + q;
        uint4 g00 = P4[r0 + (size_t)x0 * 4];
        uint4 g01 = P4[r0 + (size_t)x1 * 4];
        uint4 g10 = P4[r1 + (size_t)x0 * 4];
        uint4 g11 = P4[r1 + (size_t)x1 * 4];
        float w00 = wl * (1.f - fx) * (1.f - fy);
        float w01 = wl * fx * (1.f - fy);
        float w10 = wl * (1.f - fx) * fy;
        float w11 = wl * fx * fy;
        const unsigned* p00 = &g00.x; const unsigned* p01 = &g01.x;
        const unsigned* p10 = &g10.x; const unsigned* p11 = &g11.x;
#pragma unroll
        for (int k = 0; k < 4; k++) {
            float2 f00 = __half22float2(*(const __half2*)&p00[k]);
            float2 f01 = __half22float2(*(const __half2*)&p01[k]);
            float2 f10 = __half22float2(*(const __half2*)&p10[k]);
            float2 f11 = __half22float2(*(const __half2*)&p11[k]);
            acc[2 * k]     += w00 * f00.x + w01 * f01.x + w10 * f10.x + w11 * f11.x;
            acc[2 * k + 1] += w00 * f00.y + w01 * f01.y + w10 * f10.y + w11 * f11.y;
        }
    }
    float4* o4 = (float4*)&out[(size_t)b * 32 + q * 8];
    o4[0] = make_float4(acc[0], acc[1], acc[2], acc[3]);
    o4[1] = make_float4(acc[4], acc[5], acc[6], acc[7]);
}

extern "C" void kernel_launch(void* const* d_in, const int* in_sizes, int n_in,
                              void* d_out, int out_size) {
    const float* feat = (const float*)d_in[0];
    const float* w    = (const float*)d_in[1];
    const float* r    = (const float*)d_in[2];
    float* out = (float*)d_out;
    int B = in_sizes[2];

    k_transpose_pool1<<<dim3(8, 256, 6), 256>>>(feat);

    k_pool<<<(6 * 128 * 128 * 8 + 255) / 256, 256>>>(256, 0,      393216);
    k_pool<<<(6 *  64 *  64 * 8 + 255) / 256, 256>>>(128, 393216, 491520);
    k_pool<<<(6 *  32 *  32 * 8 + 255) / 256, 256>>>( 64, 491520, 516096);
    k_pool<<<(6 *  16 *  16 * 8 + 255) / 256, 256>>>( 32, 516096, 522240);

    k_filter_all<<<8184, 256>>>();

    long nthreads = (long)B * 4;
    k_fetch<<<(unsigned)((nthreads + 255) / 256), 256>>>(w, r, out, B);
}